// round 5
// baseline (speedup 1.0000x reference)
#include <cuda_runtime.h>
#include <cuda_bf16.h>
#include <math.h>

// Problem constants
#define BB 32
#define SS 512
#define II 512
#define HH 1024
#define OO 512
#define G4 4096          // 4*H
#define LDW 1536         // I+H, row stride of the gate weight matrices

// -------------------- scratch (device globals; no allocations) --------------------
__device__ float g_xg[(size_t)SS * BB * G4];   // [b][s][4H] row m = b*S+s   (256 MB)
__device__ float g_hs[(size_t)BB * SS * HH];   // [b][s][H]  row m = b*S+s   (64 MB)
__device__ float g_hA[BB * HH];
__device__ float g_hB[BB * HH];
__device__ float g_c [BB * HH];

// -------------------- utility kernels --------------------
__global__ void zero_hc(float* __restrict__ h, float* __restrict__ c) {
    int i = blockIdx.x * blockDim.x + threadIdx.x;
    if (i < BB * HH) { h[i] = 0.0f; c[i] = 0.0f; }
}

__global__ void copy_finals(const float* __restrict__ h, const float* __restrict__ c,
                            float* __restrict__ out) {
    int i = blockIdx.x * blockDim.x + threadIdx.x;
    if (i < BB * HH) { out[i] = h[i]; out[BB * HH + i] = c[i]; }
}

// -------------------- SGEMM: C[M,N] = A[M,K] @ Bw[N,K]^T + bias[N] --------------------
// BM=BN=128, BK=16, 256 threads, 8x8 per thread. Requires M%128==0, N%128==0, K%16==0.
__global__ __launch_bounds__(256, 2)
void sgemm_tn(int M, int N, int K,
              const float* __restrict__ A, int lda,
              const float* __restrict__ Bw, int ldb,
              const float* __restrict__ bias,
              float* __restrict__ C, int ldc) {
    __shared__ float As[16][128];
    __shared__ float Bs[16][128];

    const int tid = threadIdx.x;
    const int rowBase = blockIdx.y * 128;
    const int colBase = blockIdx.x * 128;

    const int ldRow = tid >> 2;          // 0..63
    const int ldK   = (tid & 3) << 2;    // 0,4,8,12

    const int tx = tid & 15;             // 0..15 -> N
    const int ty = tid >> 4;             // 0..15 -> M

    float acc[8][8];
#pragma unroll
    for (int i = 0; i < 8; i++)
#pragma unroll
        for (int j = 0; j < 8; j++) acc[i][j] = 0.0f;

    for (int k0 = 0; k0 < K; k0 += 16) {
        // load A tile (BM x BK) transposed into As[k][m]
#pragma unroll
        for (int r = 0; r < 128; r += 64) {
            float4 va = *reinterpret_cast<const float4*>(
                A + (size_t)(rowBase + ldRow + r) * lda + k0 + ldK);
            As[ldK + 0][ldRow + r] = va.x;
            As[ldK + 1][ldRow + r] = va.y;
            As[ldK + 2][ldRow + r] = va.z;
            As[ldK + 3][ldRow + r] = va.w;
        }
        // load B tile (BN x BK) transposed into Bs[k][n]
#pragma unroll
        for (int r = 0; r < 128; r += 64) {
            float4 vb = *reinterpret_cast<const float4*>(
                Bw + (size_t)(colBase + ldRow + r) * ldb + k0 + ldK);
            Bs[ldK + 0][ldRow + r] = vb.x;
            Bs[ldK + 1][ldRow + r] = vb.y;
            Bs[ldK + 2][ldRow + r] = vb.z;
            Bs[ldK + 3][ldRow + r] = vb.w;
        }
        __syncthreads();

#pragma unroll
        for (int kk = 0; kk < 16; kk++) {
            float ar[8], br[8];
#pragma unroll
            for (int i = 0; i < 8; i++) ar[i] = As[kk][ty * 8 + i];
#pragma unroll
            for (int j = 0; j < 8; j++) br[j] = Bs[kk][tx * 8 + j];
#pragma unroll
            for (int i = 0; i < 8; i++)
#pragma unroll
                for (int j = 0; j < 8; j++) acc[i][j] += ar[i] * br[j];
        }
        __syncthreads();
    }

    // epilogue: add bias, vectorized store
#pragma unroll
    for (int i = 0; i < 8; i++) {
        float* crow = C + (size_t)(rowBase + ty * 8 + i) * ldc + colBase + tx * 8;
#pragma unroll
        for (int j = 0; j < 8; j += 4) {
            float4 v;
            v.x = acc[i][j + 0] + bias[colBase + tx * 8 + j + 0];
            v.y = acc[i][j + 1] + bias[colBase + tx * 8 + j + 1];
            v.z = acc[i][j + 2] + bias[colBase + tx * 8 + j + 2];
            v.w = acc[i][j + 3] + bias[colBase + tx * 8 + j + 3];
            *reinterpret_cast<float4*>(crow + j) = v;
        }
    }
}

// -------------------- recurrent step --------------------
// grid = 128 blocks x 256 threads. warp w handles gate-row u = blockIdx*8 + w,
// lanes = batch b. h_prev (32x1024) is staged in smem with pitch 1028 floats
// (conflict-free LDS.128). Wh rows are uniform LDG.128 broadcasts.
#define HPITCH 1028
#define STEP_SMEM (BB * HPITCH * 4)

__global__ __launch_bounds__(256, 1)
void lstm_step(const float* __restrict__ xg,
               const float* __restrict__ h_prev, float* __restrict__ h_next,
               float* __restrict__ c, float* __restrict__ hs,
               const float* __restrict__ Wf, const float* __restrict__ Wi,
               const float* __restrict__ Wo, const float* __restrict__ Wc,
               int s) {
    extern __shared__ float hsm[];
    const int tid = threadIdx.x;

    // stage h_prev -> smem (coalesced float4)
    for (int idx = tid; idx < BB * (HH / 4); idx += 256) {
        int b  = idx >> 8;          // HH/4 = 256 float4 per row
        int k4 = idx & 255;
        float4 v = *reinterpret_cast<const float4*>(h_prev + (size_t)b * HH + k4 * 4);
        *reinterpret_cast<float4*>(hsm + (size_t)b * HPITCH + k4 * 4) = v;
    }
    __syncthreads();

    const int b = tid & 31;                       // lane = batch
    const int u = blockIdx.x * 8 + (tid >> 5);    // warp = gate row

    const float* wf = Wf + (size_t)u * LDW + II;
    const float* wi = Wi + (size_t)u * LDW + II;
    const float* wo = Wo + (size_t)u * LDW + II;
    const float* wc = Wc + (size_t)u * LDW + II;
    const float* hrow = hsm + (size_t)b * HPITCH;

    float4 af = {0,0,0,0}, ai = {0,0,0,0}, ao = {0,0,0,0}, ac = {0,0,0,0};

#pragma unroll 4
    for (int k = 0; k < HH; k += 4) {
        float4 hv = *reinterpret_cast<const float4*>(hrow + k);
        float4 vf = __ldg(reinterpret_cast<const float4*>(wf + k));
        float4 vi = __ldg(reinterpret_cast<const float4*>(wi + k));
        float4 vo = __ldg(reinterpret_cast<const float4*>(wo + k));
        float4 vc = __ldg(reinterpret_cast<const float4*>(wc + k));
        af.x += vf.x * hv.x; af.y += vf.y * hv.y; af.z += vf.z * hv.z; af.w += vf.w * hv.w;
        ai.x += vi.x * hv.x; ai.y += vi.y * hv.y; ai.z += vi.z * hv.z; ai.w += vi.w * hv.w;
        ao.x += vo.x * hv.x; ao.y += vo.y * hv.y; ao.z += vo.z * hv.z; ao.w += vo.w * hv.w;
        ac.x += vc.x * hv.x; ac.y += vc.y * hv.y; ac.z += vc.z * hv.z; ac.w += vc.w * hv.w;
    }

    const size_t m = (size_t)b * SS + s;
    const float* xr = xg + m * G4;
    float gf = (af.x + af.y) + (af.z + af.w) + xr[u];
    float gi = (ai.x + ai.y) + (ai.z + ai.w) + xr[HH + u];
    float go = (ao.x + ao.y) + (ao.z + ao.w) + xr[2 * HH + u];
    float gc = (ac.x + ac.y) + (ac.z + ac.w) + xr[3 * HH + u];

    float f = 1.0f / (1.0f + expf(-gf));
    float i = 1.0f / (1.0f + expf(-gi));
    float o = 1.0f / (1.0f + expf(-go));

    const int cu = b * HH + u;
    float cn = f * c[cu] + i * tanhf(gc);
    c[cu] = cn;
    float hn = o * tanhf(cn);
    h_next[cu] = hn;
    hs[m * HH + u] = hn;
}

// -------------------- launch --------------------
extern "C" void kernel_launch(void* const* d_in, const int* in_sizes, int n_in,
                              void* d_out, int out_size) {
    (void)in_sizes; (void)n_in;
    const float* x    = (const float*)d_in[0];
    const float* Wf_w = (const float*)d_in[1];
    const float* Wf_b = (const float*)d_in[2];
    const float* Wi_w = (const float*)d_in[3];
    const float* Wi_b = (const float*)d_in[4];
    const float* Wo_w = (const float*)d_in[5];
    const float* Wo_b = (const float*)d_in[6];
    const float* Wc_w = (const float*)d_in[7];
    const float* Wc_b = (const float*)d_in[8];
    const float* out_w = (const float*)d_in[9];
    const float* out_b = (const float*)d_in[10];

    float *xg, *hs, *hA, *hB, *c;
    cudaGetSymbolAddress((void**)&xg, g_xg);
    cudaGetSymbolAddress((void**)&hs, g_hs);
    cudaGetSymbolAddress((void**)&hA, g_hA);
    cudaGetSymbolAddress((void**)&hB, g_hB);
    cudaGetSymbolAddress((void**)&c,  g_c);

    cudaFuncSetAttribute(lstm_step, cudaFuncAttributeMaxDynamicSharedMemorySize, STEP_SMEM);

    // reset state (deterministic across graph replays)
    zero_hc<<<128, 256>>>(hA, c);

    const int M = BB * SS;  // 16384, row m = b*S+s

    // phase 1: xg[m][g] = x @ Wx^T + b   (4 gate GEMMs: N=1024, K=512)
    {
        dim3 grid(HH / 128, M / 128);
        sgemm_tn<<<grid, 256>>>(M, HH, II, x, II, Wf_w, LDW, Wf_b, xg + 0 * HH, G4);
        sgemm_tn<<<grid, 256>>>(M, HH, II, x, II, Wi_w, LDW, Wi_b, xg + 1 * HH, G4);
        sgemm_tn<<<grid, 256>>>(M, HH, II, x, II, Wo_w, LDW, Wo_b, xg + 2 * HH, G4);
        sgemm_tn<<<grid, 256>>>(M, HH, II, x, II, Wc_w, LDW, Wc_b, xg + 3 * HH, G4);
    }

    // phase 2: sequential scan, double-buffered h
    for (int s = 0; s < SS; s++) {
        const float* hp = (s & 1) ? hB : hA;
        float*       hn = (s & 1) ? hA : hB;
        lstm_step<<<128, 256, STEP_SMEM>>>(xg, hp, hn, c, hs,
                                           Wf_w, Wi_w, Wo_w, Wc_w, s);
    }
    // final h lives in hA (last write at s=511 targets hA)

    // phase 3: final = hs @ out_w^T + out_b  (M=16384, N=512, K=1024)
    {
        dim3 grid(OO / 128, M / 128);
        sgemm_tn<<<grid, 256>>>(M, OO, HH, hs, HH, out_w, HH, out_b, (float*)d_out, OO);
    }

    // tail outputs (h_fin, c_fin) if the flattened output includes them
    long long need = (long long)BB * SS * OO + 2LL * BB * HH;
    if ((long long)out_size >= need) {
        copy_finals<<<128, 256>>>(hA, c, (float*)d_out + (size_t)BB * SS * OO);
    }
}

// round 6
// speedup vs baseline: 1.0116x; 1.0116x over previous
#include <cuda_runtime.h>
#include <cuda_bf16.h>
#include <math.h>

// Problem constants
#define BB 32
#define SS 512
#define II 512
#define HH 1024
#define OO 512
#define G4 4096          // 4*H
#define LDW 1536         // I+H, row stride of the gate weight matrices

// packed fp32x2 FMA (Blackwell dual-issue fp32 pipe, PTX-only)
#define FMA2(acc, a, b) \
    asm("fma.rn.f32x2 %0, %1, %2, %0;" : "+l"(acc) : "l"(a), "l"(b))

__device__ __forceinline__ float2 unpack2(unsigned long long v) {
    float2 r;
    asm("mov.b64 {%0, %1}, %2;" : "=f"(r.x), "=f"(r.y) : "l"(v));
    return r;
}
__device__ __forceinline__ unsigned long long dup2(float x) {
    unsigned long long r;
    asm("mov.b64 %0, {%1, %1};" : "=l"(r) : "f"(x));
    return r;
}

// -------------------- scratch (device globals; no allocations) --------------------
__device__ float g_xg[(size_t)SS * BB * G4];   // [b][s][4H] row m = b*S+s   (256 MB)
__device__ float g_hs[(size_t)BB * SS * HH];   // [b][s][H]  row m = b*S+s   (64 MB)
__device__ float g_htA[BB * HH];               // h transposed pair-major: [H/2][B] float2
__device__ float g_htB[BB * HH];
__device__ float g_c [BB * HH];                // c transposed: [u][b]

// -------------------- utility kernels --------------------
__global__ void zero_hc(float* __restrict__ h, float* __restrict__ c) {
    int i = blockIdx.x * blockDim.x + threadIdx.x;
    if (i < BB * HH) { h[i] = 0.0f; c[i] = 0.0f; }
}

// final h is in pair-major transposed layout, c in [u][b]; emit [b][H] for both
__global__ void copy_finals(const float* __restrict__ ht, const float* __restrict__ c,
                            float* __restrict__ out) {
    int i = blockIdx.x * blockDim.x + threadIdx.x;   // i = b*HH + u
    if (i < BB * HH) {
        int b = i >> 10, u = i & (HH - 1);
        out[i]           = ht[(u >> 1) * (2 * BB) + 2 * b + (u & 1)];
        out[BB * HH + i] = c[u * BB + b];
    }
}

// -------------------- SGEMM: C[M,N] = A[M,K] @ Bw[N,K]^T + bias[N] --------------------
// BM=BN=128, BK=16, 256 threads, 8x8 per thread, packed f32x2 inner product.
__global__ __launch_bounds__(256, 2)
void sgemm_tn(int M, int N, int K,
              const float* __restrict__ A, int lda,
              const float* __restrict__ Bw, int ldb,
              const float* __restrict__ bias,
              float* __restrict__ C, int ldc) {
    __shared__ float As[16][128];
    __shared__ float Bs[16][128];

    const int tid = threadIdx.x;
    const int rowBase = blockIdx.y * 128;
    const int colBase = blockIdx.x * 128;

    const int ldRow = tid >> 2;          // 0..63
    const int ldK   = (tid & 3) << 2;    // 0,4,8,12

    const int tx = tid & 15;             // 0..15 -> N
    const int ty = tid >> 4;             // 0..15 -> M

    unsigned long long acc[8][4];        // [mi][nj-pair] packed f32x2
#pragma unroll
    for (int i = 0; i < 8; i++)
#pragma unroll
        for (int j = 0; j < 4; j++) acc[i][j] = 0ull;  // (+0.f, +0.f)

    for (int k0 = 0; k0 < K; k0 += 16) {
#pragma unroll
        for (int r = 0; r < 128; r += 64) {
            float4 va = *reinterpret_cast<const float4*>(
                A + (size_t)(rowBase + ldRow + r) * lda + k0 + ldK);
            As[ldK + 0][ldRow + r] = va.x;
            As[ldK + 1][ldRow + r] = va.y;
            As[ldK + 2][ldRow + r] = va.z;
            As[ldK + 3][ldRow + r] = va.w;
        }
#pragma unroll
        for (int r = 0; r < 128; r += 64) {
            float4 vb = *reinterpret_cast<const float4*>(
                Bw + (size_t)(colBase + ldRow + r) * ldb + k0 + ldK);
            Bs[ldK + 0][ldRow + r] = vb.x;
            Bs[ldK + 1][ldRow + r] = vb.y;
            Bs[ldK + 2][ldRow + r] = vb.z;
            Bs[ldK + 3][ldRow + r] = vb.w;
        }
        __syncthreads();

#pragma unroll
        for (int kk = 0; kk < 16; kk++) {
            float ar[8];
#pragma unroll
            for (int i = 0; i < 8; i++) ar[i] = As[kk][ty * 8 + i];
            const ulonglong2* bp =
                reinterpret_cast<const ulonglong2*>(&Bs[kk][tx * 8]);
            ulonglong2 b01 = bp[0];     // n-pairs (0,1) and (2,3)
            ulonglong2 b23 = bp[1];     // n-pairs (4,5) and (6,7)
#pragma unroll
            for (int i = 0; i < 8; i++) {
                unsigned long long a2 = dup2(ar[i]);
                FMA2(acc[i][0], a2, b01.x);
                FMA2(acc[i][1], a2, b01.y);
                FMA2(acc[i][2], a2, b23.x);
                FMA2(acc[i][3], a2, b23.y);
            }
        }
        __syncthreads();
    }

#pragma unroll
    for (int i = 0; i < 8; i++) {
        float* crow = C + (size_t)(rowBase + ty * 8 + i) * ldc + colBase + tx * 8;
#pragma unroll
        for (int j = 0; j < 2; j++) {
            float2 p0 = unpack2(acc[i][2 * j + 0]);
            float2 p1 = unpack2(acc[i][2 * j + 1]);
            float4 v;
            v.x = p0.x + bias[colBase + tx * 8 + 4 * j + 0];
            v.y = p0.y + bias[colBase + tx * 8 + 4 * j + 1];
            v.z = p1.x + bias[colBase + tx * 8 + 4 * j + 2];
            v.w = p1.y + bias[colBase + tx * 8 + 4 * j + 3];
            *reinterpret_cast<float4*>(crow + 4 * j) = v;
        }
    }
}

// -------------------- recurrent step --------------------
// 128 blocks x 256 threads. warp w handles gate-row u = blockIdx*8 + w,
// lanes = batch b. h_prev lives in global pair-major layout h_t[k/2][b] (float2),
// staged into smem by a LINEAR copy (no transpose -> no bank conflicts).
// Compute reads hp2[k2][b]: 32 consecutive float2 per warp -> conflict-free LDS.64.
// Weight rows: uniform LDG.128 broadcasts reinterpreted as packed f32x2 pairs.
#define STEP_SMEM (512 * BB * 8)   // 512 pair-rows x 32 batches x float2 = 128 KB

__global__ __launch_bounds__(256, 1)
void lstm_step(const float* __restrict__ xg,
               const float* __restrict__ ht_prev, float* __restrict__ ht_next,
               float* __restrict__ c, float* __restrict__ hs,
               const float* __restrict__ Wf, const float* __restrict__ Wi,
               const float* __restrict__ Wo, const float* __restrict__ Wc,
               int s) {
    extern __shared__ float2 hp2[];          // [512][32]
    const int tid = threadIdx.x;
    const int b = tid & 31;                  // lane = batch
    const int u = blockIdx.x * 8 + (tid >> 5);

    // issue tail loads early (DRAM latency overlap with staging)
    const size_t m = (size_t)b * SS + s;
    const float* xr = xg + m * G4;
    float xf = xr[u];
    float xi = xr[HH + u];
    float xo = xr[2 * HH + u];
    float xc = xr[3 * HH + u];
    float cprev = c[u * BB + b];             // coalesced

    // stage h_t -> smem, straight linear copy of 128 KB
    {
        const ulonglong2* src = reinterpret_cast<const ulonglong2*>(ht_prev);
        ulonglong2* dst = reinterpret_cast<ulonglong2*>(hp2);
        for (int i = tid; i < (512 * BB * 8) / 16; i += 256) dst[i] = src[i];
    }
    __syncthreads();

    const ulonglong2* wf = reinterpret_cast<const ulonglong2*>(Wf + (size_t)u * LDW + II);
    const ulonglong2* wi = reinterpret_cast<const ulonglong2*>(Wi + (size_t)u * LDW + II);
    const ulonglong2* wo = reinterpret_cast<const ulonglong2*>(Wo + (size_t)u * LDW + II);
    const ulonglong2* wc = reinterpret_cast<const ulonglong2*>(Wc + (size_t)u * LDW + II);

    unsigned long long af0 = 0ull, af1 = 0ull, ai0 = 0ull, ai1 = 0ull;
    unsigned long long ao0 = 0ull, ao1 = 0ull, ac0 = 0ull, ac1 = 0ull;

#pragma unroll 4
    for (int k2 = 0; k2 < 512; k2 += 2) {
        // h pairs (k, k+1) and (k+2, k+3) for this batch lane
        unsigned long long h0 =
            *reinterpret_cast<const unsigned long long*>(&hp2[k2 * BB + b]);
        unsigned long long h1 =
            *reinterpret_cast<const unsigned long long*>(&hp2[(k2 + 1) * BB + b]);
        ulonglong2 vf = wf[k2 >> 1];   // floats 2*k2 .. 2*k2+3
        ulonglong2 vi = wi[k2 >> 1];
        ulonglong2 vo = wo[k2 >> 1];
        ulonglong2 vc = wc[k2 >> 1];
        FMA2(af0, vf.x, h0); FMA2(af1, vf.y, h1);
        FMA2(ai0, vi.x, h0); FMA2(ai1, vi.y, h1);
        FMA2(ao0, vo.x, h0); FMA2(ao1, vo.y, h1);
        FMA2(ac0, vc.x, h0); FMA2(ac1, vc.y, h1);
    }

    float2 f0 = unpack2(af0), f1 = unpack2(af1);
    float2 i0 = unpack2(ai0), i1 = unpack2(ai1);
    float2 o0 = unpack2(ao0), o1 = unpack2(ao1);
    float2 c0 = unpack2(ac0), c1 = unpack2(ac1);

    float gf = (f0.x + f0.y) + (f1.x + f1.y) + xf;
    float gi = (i0.x + i0.y) + (i1.x + i1.y) + xi;
    float go = (o0.x + o0.y) + (o1.x + o1.y) + xo;
    float gc = (c0.x + c0.y) + (c1.x + c1.y) + xc;

    float f = 1.0f / (1.0f + expf(-gf));
    float i = 1.0f / (1.0f + expf(-gi));
    float o = 1.0f / (1.0f + expf(-go));

    float cn = f * cprev + i * tanhf(gc);
    c[u * BB + b] = cn;
    float hn = o * tanhf(cn);

    // write h_next in pair-major transposed layout (ready for next step's staging)
    ht_next[(u >> 1) * (2 * BB) + 2 * b + (u & 1)] = hn;
    // and in [b][s][H] layout for the output projection
    hs[m * HH + u] = hn;
}

// -------------------- launch --------------------
extern "C" void kernel_launch(void* const* d_in, const int* in_sizes, int n_in,
                              void* d_out, int out_size) {
    (void)in_sizes; (void)n_in;
    const float* x    = (const float*)d_in[0];
    const float* Wf_w = (const float*)d_in[1];
    const float* Wf_b = (const float*)d_in[2];
    const float* Wi_w = (const float*)d_in[3];
    const float* Wi_b = (const float*)d_in[4];
    const float* Wo_w = (const float*)d_in[5];
    const float* Wo_b = (const float*)d_in[6];
    const float* Wc_w = (const float*)d_in[7];
    const float* Wc_b = (const float*)d_in[8];
    const float* out_w = (const float*)d_in[9];
    const float* out_b = (const float*)d_in[10];

    float *xg, *hs, *hA, *hB, *c;
    cudaGetSymbolAddress((void**)&xg, g_xg);
    cudaGetSymbolAddress((void**)&hs, g_hs);
    cudaGetSymbolAddress((void**)&hA, g_htA);
    cudaGetSymbolAddress((void**)&hB, g_htB);
    cudaGetSymbolAddress((void**)&c,  g_c);

    cudaFuncSetAttribute(lstm_step, cudaFuncAttributeMaxDynamicSharedMemorySize, STEP_SMEM);

    // reset state (deterministic across graph replays)
    zero_hc<<<128, 256>>>(hA, c);

    const int M = BB * SS;  // 16384, row m = b*S+s

    // phase 1: xg[m][g] = x @ Wx^T + b   (4 gate GEMMs: N=1024, K=512)
    {
        dim3 grid(HH / 128, M / 128);
        sgemm_tn<<<grid, 256>>>(M, HH, II, x, II, Wf_w, LDW, Wf_b, xg + 0 * HH, G4);
        sgemm_tn<<<grid, 256>>>(M, HH, II, x, II, Wi_w, LDW, Wi_b, xg + 1 * HH, G4);
        sgemm_tn<<<grid, 256>>>(M, HH, II, x, II, Wo_w, LDW, Wo_b, xg + 2 * HH, G4);
        sgemm_tn<<<grid, 256>>>(M, HH, II, x, II, Wc_w, LDW, Wc_b, xg + 3 * HH, G4);
    }

    // phase 2: sequential scan, double-buffered transposed h
    for (int s = 0; s < SS; s++) {
        const float* hp = (s & 1) ? hB : hA;
        float*       hn = (s & 1) ? hA : hB;
        lstm_step<<<128, 256, STEP_SMEM>>>(xg, hp, hn, c, hs,
                                           Wf_w, Wi_w, Wo_w, Wc_w, s);
    }
    // final h (s=511 writes) lives in hA

    // phase 3: final = hs @ out_w^T + out_b  (M=16384, N=512, K=1024)
    {
        dim3 grid(OO / 128, M / 128);
        sgemm_tn<<<grid, 256>>>(M, OO, HH, hs, HH, out_w, HH, out_b, (float*)d_out, OO);
    }

    // tail outputs (h_fin, c_fin) if the flattened output includes them
    long long need = (long long)BB * SS * OO + 2LL * BB * HH;
    if ((long long)out_size >= need) {
        copy_finals<<<128, 256>>>(hA, c, (float*)d_out + (size_t)BB * SS * OO);
    }
}

// round 12
// speedup vs baseline: 1.7344x; 1.7144x over previous
#include <cuda_runtime.h>
#include <cuda_bf16.h>
#include <math.h>

// Problem constants
#define BB 32
#define SS 512
#define II 512
#define HH 1024
#define OO 512
#define G4 4096          // 4*H
#define LDW 1536         // I+H, row stride of the gate weight matrices
#define NB 128           // persistent scan blocks (1 per SM, <= 148)

// packed fp32x2 FMA
#define FMA2(acc, a, b) \
    asm("fma.rn.f32x2 %0, %1, %2, %0;" : "+l"(acc) : "l"(a), "l"(b))

__device__ __forceinline__ float2 unpack2(unsigned long long v) {
    float2 r;
    asm("mov.b64 {%0, %1}, %2;" : "=f"(r.x), "=f"(r.y) : "l"(v));
    return r;
}
__device__ __forceinline__ unsigned long long dup2(float x) {
    unsigned long long r;
    asm("mov.b64 %0, {%1, %1};" : "=l"(r) : "f"(x));
    return r;
}

// -------------------- scratch (device globals; no allocations) --------------------
__device__ float g_xg[(size_t)SS * BB * G4];   // [b][s][4H] row m = b*S+s   (256 MB)
__device__ float g_hs[(size_t)BB * SS * HH];   // [b][s][H]  row m = b*S+s   (64 MB)
__device__ float g_htA[BB * HH];               // h quad-major: [H/4][B] float4
__device__ float g_htB[BB * HH];
__device__ float g_c [BB * HH];                // c transposed: [u][b]
__device__ unsigned g_bar;                     // CG-style barrier counter

// -------------------- utility kernels --------------------
__global__ void scan_init(float* __restrict__ hA, unsigned* __restrict__ bar) {
    int i = blockIdx.x * blockDim.x + threadIdx.x;
    if (i < BB * HH) hA[i] = 0.0f;
    if (i == 0) *bar = 0u;
}

// final h quad-major [u>>2][b][u&3], c in [u][b]; emit [b][H] for both
__global__ void copy_finals(const float* __restrict__ ht, const float* __restrict__ c,
                            float* __restrict__ out) {
    int i = blockIdx.x * blockDim.x + threadIdx.x;   // i = b*HH + u
    if (i < BB * HH) {
        int b = i >> 10, u = i & (HH - 1);
        out[i]           = ht[((u >> 2) * 32 + b) * 4 + (u & 3)];
        out[BB * HH + i] = c[u * BB + b];
    }
}

// -------------------- SGEMM: C[M,N] = A[M,K] @ Bw[N,K]^T + bias[N] --------------------
// BM=BN=128, BK=16, 256 threads, 8x8 per thread. (At fp32 SIMT peak.)
__global__ __launch_bounds__(256, 2)
void sgemm_tn(int M, int N, int K,
              const float* __restrict__ A, int lda,
              const float* __restrict__ Bw, int ldb,
              const float* __restrict__ bias,
              float* __restrict__ C, int ldc) {
    __shared__ float As[16][128];
    __shared__ float Bs[16][128];

    const int tid = threadIdx.x;
    const int rowBase = blockIdx.y * 128;
    const int colBase = blockIdx.x * 128;

    const int ldRow = tid >> 2;
    const int ldK   = (tid & 3) << 2;

    const int tx = tid & 15;
    const int ty = tid >> 4;

    unsigned long long acc[8][4];
#pragma unroll
    for (int i = 0; i < 8; i++)
#pragma unroll
        for (int j = 0; j < 4; j++) acc[i][j] = 0ull;

    for (int k0 = 0; k0 < K; k0 += 16) {
#pragma unroll
        for (int r = 0; r < 128; r += 64) {
            float4 va = *reinterpret_cast<const float4*>(
                A + (size_t)(rowBase + ldRow + r) * lda + k0 + ldK);
            As[ldK + 0][ldRow + r] = va.x;
            As[ldK + 1][ldRow + r] = va.y;
            As[ldK + 2][ldRow + r] = va.z;
            As[ldK + 3][ldRow + r] = va.w;
        }
#pragma unroll
        for (int r = 0; r < 128; r += 64) {
            float4 vb = *reinterpret_cast<const float4*>(
                Bw + (size_t)(colBase + ldRow + r) * ldb + k0 + ldK);
            Bs[ldK + 0][ldRow + r] = vb.x;
            Bs[ldK + 1][ldRow + r] = vb.y;
            Bs[ldK + 2][ldRow + r] = vb.z;
            Bs[ldK + 3][ldRow + r] = vb.w;
        }
        __syncthreads();

#pragma unroll
        for (int kk = 0; kk < 16; kk++) {
            float ar[8];
#pragma unroll
            for (int i = 0; i < 8; i++) ar[i] = As[kk][ty * 8 + i];
            const ulonglong2* bp =
                reinterpret_cast<const ulonglong2*>(&Bs[kk][tx * 8]);
            ulonglong2 b01 = bp[0];
            ulonglong2 b23 = bp[1];
#pragma unroll
            for (int i = 0; i < 8; i++) {
                unsigned long long a2 = dup2(ar[i]);
                FMA2(acc[i][0], a2, b01.x);
                FMA2(acc[i][1], a2, b01.y);
                FMA2(acc[i][2], a2, b23.x);
                FMA2(acc[i][3], a2, b23.y);
            }
        }
        __syncthreads();
    }

#pragma unroll
    for (int i = 0; i < 8; i++) {
        float* crow = C + (size_t)(rowBase + ty * 8 + i) * ldc + colBase + tx * 8;
#pragma unroll
        for (int j = 0; j < 2; j++) {
            float2 p0 = unpack2(acc[i][2 * j + 0]);
            float2 p1 = unpack2(acc[i][2 * j + 1]);
            float4 v;
            v.x = p0.x + bias[colBase + tx * 8 + 4 * j + 0];
            v.y = p0.y + bias[colBase + tx * 8 + 4 * j + 1];
            v.z = p1.x + bias[colBase + tx * 8 + 4 * j + 2];
            v.w = p1.y + bias[colBase + tx * 8 + 4 * j + 3];
            *reinterpret_cast<float4*>(crow + 4 * j) = v;
        }
    }
}

// -------------------- grid-wide barrier (cooperative-groups sync_grids pattern) ----
// fence(release) -> atomicAdd with sense in bit 31 -> volatile spin on flip ->
// fence(acquire; CCTL.IVALL flushes L1D so subsequent plain loads are coherent).
__device__ __forceinline__ void grid_sync(unsigned* bar) {
    __syncthreads();
    if (threadIdx.x == 0) {
        __threadfence();
        unsigned add = (blockIdx.x == 0) ? (0x80000000u - (NB - 1)) : 1u;
        unsigned old = atomicAdd(bar, add);
        while (((old ^ *(volatile unsigned*)bar) & 0x80000000u) == 0u) { }
        __threadfence();
    }
    __syncthreads();
}

// -------------------- persistent recurrent scan --------------------
// 128 blocks x 256 threads, one block per SM, all 512 steps in one launch.
// Block bk owns gate-rows u in [bk*8, bk*8+8); warp w = one u (all 4 gates),
// lane = batch. Weights (128 KB/block) live in smem for the whole kernel:
//   wsm[w][k2][gate] = float2 -> warp-uniform LDS.128.
// h double-buffered in global quad-major layout ht[k4][b] = float4 of
// h[4k4..4k4+3][b]; plain LDG.128 with an 8-deep prefetch ring (fresh from L2:
// the barrier's fence invalidated L1). c stays in a register across all steps.
#define SCAN_SMEM 131072

#define SCAN_FMA8()                                              \
    do {                                                          \
        FMA2(aF0, A0.x, hv.x); FMA2(aI0, A0.y, hv.x);             \
        FMA2(aO0, A1.x, hv.x); FMA2(aC0, A1.y, hv.x);             \
        FMA2(aF1, B0.x, hv.y); FMA2(aI1, B0.y, hv.y);             \
        FMA2(aO1, B1.x, hv.y); FMA2(aC1, B1.y, hv.y);             \
    } while (0)

__global__ __launch_bounds__(256, 1)
void lstm_scan(const float* __restrict__ xg,
               float* bufA, float* bufB,
               float* __restrict__ cfin, float* __restrict__ hs,
               unsigned* bar,
               const float* __restrict__ Wf, const float* __restrict__ Wi,
               const float* __restrict__ Wo, const float* __restrict__ Wc) {
    extern __shared__ float wsm[];   // [8][512][4] float2 = 128 KB
    const int tid = threadIdx.x;
    const int bk  = blockIdx.x;
    const int b   = tid & 31;        // lane = batch
    const int w   = tid >> 5;        // warp = row within block
    const int u   = bk * 8 + w;      // global gate-row

    // one-time: weights -> smem (coalesced global reads)
    for (int i = tid; i < 4 * 8 * 1024; i += 256) {
        int g  = i >> 13;            // gate
        int ww = (i >> 10) & 7;      // warp-row
        int k  = i & 1023;
        const float* Wsrc = (g == 0) ? Wf : (g == 1) ? Wi : (g == 2) ? Wo : Wc;
        float v = Wsrc[(size_t)(bk * 8 + ww) * LDW + II + k];
        wsm[(((ww * 512 + (k >> 1)) * 4 + g) << 1) + (k & 1)] = v;
    }
    __syncthreads();

    const ulonglong2* wq = reinterpret_cast<const ulonglong2*>(wsm) + (size_t)w * 1024;

    float creg = 0.0f;
    float* cur = bufA;
    float* nxt = bufB;

    for (int s = 0; s < SS; s++) {
        // prefetch this step's xg tail values (consumed ~8K cyc later)
        const float* xr = xg + ((size_t)b * SS + s) * G4;
        float xf = xr[u];
        float xi = xr[HH + u];
        float xo = xr[2 * HH + u];
        float xc = xr[3 * HH + u];

        unsigned long long aF0 = 0ull, aF1 = 0ull, aI0 = 0ull, aI1 = 0ull;
        unsigned long long aO0 = 0ull, aO1 = 0ull, aC0 = 0ull, aC1 = 0ull;

        const ulonglong2* hq = reinterpret_cast<const ulonglong2*>(cur) + b;

        // 8-deep h prefetch ring (MLP=8 on the L2 stream)
        ulonglong2 hbuf[8];
#pragma unroll
        for (int j = 0; j < 8; j++) hbuf[j] = hq[j * 32];

#pragma unroll 8
        for (int k4 = 0; k4 < 248; k4++) {
            ulonglong2 hv = hbuf[k4 & 7];
            hbuf[k4 & 7] = hq[(k4 + 8) * 32];
            ulonglong2 A0 = wq[k4 * 4 + 0];
            ulonglong2 A1 = wq[k4 * 4 + 1];
            ulonglong2 B0 = wq[k4 * 4 + 2];
            ulonglong2 B1 = wq[k4 * 4 + 3];
            SCAN_FMA8();
        }
#pragma unroll
        for (int k4 = 248; k4 < 256; k4++) {
            ulonglong2 hv = hbuf[k4 & 7];
            ulonglong2 A0 = wq[k4 * 4 + 0];
            ulonglong2 A1 = wq[k4 * 4 + 1];
            ulonglong2 B0 = wq[k4 * 4 + 2];
            ulonglong2 B1 = wq[k4 * 4 + 3];
            SCAN_FMA8();
        }

        float2 t;
        t = unpack2(aF0); float gf = t.x + t.y;
        t = unpack2(aF1); gf += t.x + t.y; gf += xf;
        t = unpack2(aI0); float gi = t.x + t.y;
        t = unpack2(aI1); gi += t.x + t.y; gi += xi;
        t = unpack2(aO0); float go = t.x + t.y;
        t = unpack2(aO1); go += t.x + t.y; go += xo;
        t = unpack2(aC0); float gc = t.x + t.y;
        t = unpack2(aC1); gc += t.x + t.y; gc += xc;

        float f  = 1.0f / (1.0f + expf(-gf));
        float ig = 1.0f / (1.0f + expf(-gi));
        float og = 1.0f / (1.0f + expf(-go));

        float cn = f * creg + ig * tanhf(gc);
        creg = cn;
        float hn = og * tanhf(cn);

        // h_next in quad-major layout + hs in [b][s][H]
        nxt[((u >> 2) * 32 + b) * 4 + (u & 3)] = hn;
        hs[((size_t)b * SS + s) * HH + u] = hn;

        grid_sync(bar);

        float* tmp = cur; cur = nxt; nxt = tmp;
    }
    // after 512 steps (even count) final h sits in bufA; write final c
    cfin[u * BB + b] = creg;
}

// -------------------- launch --------------------
extern "C" void kernel_launch(void* const* d_in, const int* in_sizes, int n_in,
                              void* d_out, int out_size) {
    (void)in_sizes; (void)n_in;
    const float* x    = (const float*)d_in[0];
    const float* Wf_w = (const float*)d_in[1];
    const float* Wf_b = (const float*)d_in[2];
    const float* Wi_w = (const float*)d_in[3];
    const float* Wi_b = (const float*)d_in[4];
    const float* Wo_w = (const float*)d_in[5];
    const float* Wo_b = (const float*)d_in[6];
    const float* Wc_w = (const float*)d_in[7];
    const float* Wc_b = (const float*)d_in[8];
    const float* out_w = (const float*)d_in[9];
    const float* out_b = (const float*)d_in[10];

    float *xg, *hs, *hA, *hB, *c;
    unsigned* bar;
    cudaGetSymbolAddress((void**)&xg, g_xg);
    cudaGetSymbolAddress((void**)&hs, g_hs);
    cudaGetSymbolAddress((void**)&hA, g_htA);
    cudaGetSymbolAddress((void**)&hB, g_htB);
    cudaGetSymbolAddress((void**)&c,  g_c);
    cudaGetSymbolAddress((void**)&bar, g_bar);

    cudaFuncSetAttribute(lstm_scan, cudaFuncAttributeMaxDynamicSharedMemorySize, SCAN_SMEM);

    // reset h0 and barrier counter (deterministic across graph replays)
    scan_init<<<128, 256>>>(hA, bar);

    const int M = BB * SS;  // 16384, row m = b*S+s

    // phase 1: xg[m][g] = x @ Wx^T + b   (4 gate GEMMs: N=1024, K=512)
    {
        dim3 grid(HH / 128, M / 128);
        sgemm_tn<<<grid, 256>>>(M, HH, II, x, II, Wf_w, LDW, Wf_b, xg + 0 * HH, G4);
        sgemm_tn<<<grid, 256>>>(M, HH, II, x, II, Wi_w, LDW, Wi_b, xg + 1 * HH, G4);
        sgemm_tn<<<grid, 256>>>(M, HH, II, x, II, Wo_w, LDW, Wo_b, xg + 2 * HH, G4);
        sgemm_tn<<<grid, 256>>>(M, HH, II, x, II, Wc_w, LDW, Wc_b, xg + 3 * HH, G4);
    }

    // phase 2: ONE persistent launch for all 512 steps
    lstm_scan<<<NB, 256, SCAN_SMEM>>>(xg, hA, hB, c, hs, bar,
                                      Wf_w, Wi_w, Wo_w, Wc_w);

    // phase 3: final = hs @ out_w^T + out_b  (M=16384, N=512, K=1024)
    {
        dim3 grid(OO / 128, M / 128);
        sgemm_tn<<<grid, 256>>>(M, OO, HH, hs, HH, out_w, HH, out_b, (float*)d_out, OO);
    }

    // tail outputs (h_fin, c_fin) if the flattened output includes them
    long long need = (long long)BB * SS * OO + 2LL * BB * HH;
    if ((long long)out_size >= need) {
        copy_finals<<<128, 256>>>(hA, c, (float*)d_out + (size_t)BB * SS * OO);
    }
}